// round 3
// baseline (speedup 1.0000x reference)
#include <cuda_runtime.h>

// Problem dimensions (fixed by setup_inputs)
#define B_DIM 4096
#define NG    2048
#define NV    128
#define NP    1024
#define MAX_ITERS 20
#define INF_LR   0.05f
#define LAMBDA_Z 1e-4f

// GEMM tiling
#define BM 128
#define BN 128
#define BK 16
#define TM 8
#define TN 8
#define APAD 4

// Scratch (allocation-free rule: __device__ globals)
__device__ float g_G [B_DIM * NG];   // g(v, prev_z), constant across iters
__device__ float g_z [B_DIM * NG];   // current z
__device__ float g_E [B_DIM * NP];   // (1 - pred^2) * (p - pred)
__device__ float g_WT[NG * NP];      // Wout transposed -> [Ng, Np], K-major for U-GEMM

// ---------------------------------------------------------------------------
// Core fp32 GEMM accumulate: C[M,N] += A[M,K] * W[N,K]^T  (both K-major)
// Block 256 threads, 128x128 tile, 8x8 per thread, BK=16 k-slab.
// ---------------------------------------------------------------------------
__device__ __forceinline__ void gemm_accum(
    const float* __restrict__ A, int lda,
    const float* __restrict__ W, int ldw,
    int kTiles, int by, int bx,
    float acc[TM][TN],
    float As[BK][BM + APAD], float Bs[BK][BN + APAD])
{
    const int tid  = threadIdx.x;
    const int tx   = tid & 15;
    const int ty   = tid >> 4;
    const int row4 = tid >> 2;          // 0..63
    const int col4 = (tid & 3) * 4;     // 0,4,8,12

    const float* Abase = A + (size_t)(by * BM) * lda;
    const float* Wbase = W + (size_t)(bx * BN) * ldw;

    for (int kt = 0; kt < kTiles; ++kt) {
        const int kof = kt * BK + col4;
        #pragma unroll
        for (int i = 0; i < 2; ++i) {
            int r = row4 + i * 64;
            float4 va = *(const float4*)(Abase + (size_t)r * lda + kof);
            As[col4 + 0][r] = va.x; As[col4 + 1][r] = va.y;
            As[col4 + 2][r] = va.z; As[col4 + 3][r] = va.w;
            float4 vb = *(const float4*)(Wbase + (size_t)r * ldw + kof);
            Bs[col4 + 0][r] = vb.x; Bs[col4 + 1][r] = vb.y;
            Bs[col4 + 2][r] = vb.z; Bs[col4 + 3][r] = vb.w;
        }
        __syncthreads();
        #pragma unroll
        for (int k = 0; k < BK; ++k) {
            float a[TM], b[TN];
            #pragma unroll
            for (int i = 0; i < TM; ++i) a[i] = As[k][ty * TM + i];
            #pragma unroll
            for (int j = 0; j < TN; ++j) b[j] = Bs[k][tx * TN + j];
            #pragma unroll
            for (int i = 0; i < TM; ++i)
                #pragma unroll
                for (int j = 0; j < TN; ++j)
                    acc[i][j] = fmaf(a[i], b[j], acc[i][j]);
        }
        __syncthreads();
    }
}

// ---------------------------------------------------------------------------
// Wout [Np, Ng] -> WT [Ng, Np]
// ---------------------------------------------------------------------------
__global__ void k_transpose(const float* __restrict__ Wout)
{
    __shared__ float tile[32][33];
    int x = blockIdx.x * 32 + threadIdx.x;   // g index in Wout
    int y = blockIdx.y * 32 + threadIdx.y;   // np index in Wout
    #pragma unroll
    for (int i = 0; i < 32; i += 8)
        tile[threadIdx.y + i][threadIdx.x] = Wout[(size_t)(y + i) * NG + x];
    __syncthreads();
    int xo = blockIdx.y * 32 + threadIdx.x;  // np index in WT
    int yo = blockIdx.x * 32 + threadIdx.y;  // g index in WT
    #pragma unroll
    for (int i = 0; i < 32; i += 8)
        g_WT[(size_t)(yo + i) * NP + xo] = tile[threadIdx.x][threadIdx.y + i];
}

// ---------------------------------------------------------------------------
// K1: G = tanh(prev_z @ Wr^T + v @ Win^T); z = G
// ---------------------------------------------------------------------------
__global__ __launch_bounds__(256) void k_gval(
    const float* __restrict__ prev_z, const float* __restrict__ Wr,
    const float* __restrict__ v,      const float* __restrict__ Win)
{
    __shared__ float As[BK][BM + APAD], Bs[BK][BN + APAD];
    float acc[TM][TN];
    #pragma unroll
    for (int i = 0; i < TM; ++i)
        #pragma unroll
        for (int j = 0; j < TN; ++j) acc[i][j] = 0.f;

    int bx = blockIdx.x, by = blockIdx.y;
    gemm_accum(prev_z, NG, Wr,  NG, NG / BK, by, bx, acc, As, Bs);
    gemm_accum(v,      NV, Win, NV, NV / BK, by, bx, acc, As, Bs);

    int tx = threadIdx.x & 15, ty = threadIdx.x >> 4;
    int row0 = by * BM + ty * TM, col0 = bx * BN + tx * TN;
    #pragma unroll
    for (int i = 0; i < TM; ++i) {
        float gv[TN];
        #pragma unroll
        for (int j = 0; j < TN; ++j) gv[j] = tanhf(acc[i][j]);
        size_t idx = (size_t)(row0 + i) * NG + col0;
        float4 f0 = make_float4(gv[0], gv[1], gv[2], gv[3]);
        float4 f1 = make_float4(gv[4], gv[5], gv[6], gv[7]);
        *(float4*)(g_G + idx)     = f0;
        *(float4*)(g_G + idx + 4) = f1;
        *(float4*)(g_z + idx)     = f0;
        *(float4*)(g_z + idx + 4) = f1;
    }
}

// ---------------------------------------------------------------------------
// K2: pred = tanh(z @ Wout^T);  E = (1 - pred^2) * (p - pred)
// ---------------------------------------------------------------------------
__global__ __launch_bounds__(256) void k_pred(
    const float* __restrict__ Wout, const float* __restrict__ p)
{
    __shared__ float As[BK][BM + APAD], Bs[BK][BN + APAD];
    float acc[TM][TN];
    #pragma unroll
    for (int i = 0; i < TM; ++i)
        #pragma unroll
        for (int j = 0; j < TN; ++j) acc[i][j] = 0.f;

    int bx = blockIdx.x, by = blockIdx.y;
    gemm_accum(g_z, NG, Wout, NG, NG / BK, by, bx, acc, As, Bs);

    int tx = threadIdx.x & 15, ty = threadIdx.x >> 4;
    int row0 = by * BM + ty * TM, col0 = bx * BN + tx * TN;
    #pragma unroll
    for (int i = 0; i < TM; ++i) {
        size_t idx = (size_t)(row0 + i) * NP + col0;
        float4 p0 = *(const float4*)(p + idx);
        float4 p1 = *(const float4*)(p + idx + 4);
        float pv[TN] = {p0.x, p0.y, p0.z, p0.w, p1.x, p1.y, p1.z, p1.w};
        float ev[TN];
        #pragma unroll
        for (int j = 0; j < TN; ++j) {
            float pred = tanhf(acc[i][j]);
            ev[j] = (1.0f - pred * pred) * (pv[j] - pred);
        }
        *(float4*)(g_E + idx)     = make_float4(ev[0], ev[1], ev[2], ev[3]);
        *(float4*)(g_E + idx + 4) = make_float4(ev[4], ev[5], ev[6], ev[7]);
    }
}

// ---------------------------------------------------------------------------
// K3: U = E @ Wout (via WT);  z -= INF_LR * ((z - G) - U + LAMBDA_Z*sign(z))
// Guarded by device-side inf_iters so the fixed 20-launch graph is correct
// for any inf_iters <= 20.
// ---------------------------------------------------------------------------
__global__ __launch_bounds__(256) void k_update(
    const int* __restrict__ n_iters, int iter)
{
    if (iter >= *n_iters) return;

    __shared__ float As[BK][BM + APAD], Bs[BK][BN + APAD];
    float acc[TM][TN];
    #pragma unroll
    for (int i = 0; i < TM; ++i)
        #pragma unroll
        for (int j = 0; j < TN; ++j) acc[i][j] = 0.f;

    int bx = blockIdx.x, by = blockIdx.y;
    gemm_accum(g_E, NP, g_WT, NP, NP / BK, by, bx, acc, As, Bs);

    int tx = threadIdx.x & 15, ty = threadIdx.x >> 4;
    int row0 = by * BM + ty * TM, col0 = bx * BN + tx * TN;
    #pragma unroll
    for (int i = 0; i < TM; ++i) {
        size_t idx = (size_t)(row0 + i) * NG + col0;
        float4 z0 = *(const float4*)(g_z + idx);
        float4 z1 = *(const float4*)(g_z + idx + 4);
        float4 ga = *(const float4*)(g_G + idx);
        float4 gb = *(const float4*)(g_G + idx + 4);
        float zv[TN] = {z0.x, z0.y, z0.z, z0.w, z1.x, z1.y, z1.z, z1.w};
        float gv[TN] = {ga.x, ga.y, ga.z, ga.w, gb.x, gb.y, gb.z, gb.w};
        float zn[TN];
        #pragma unroll
        for (int j = 0; j < TN; ++j) {
            float zo  = zv[j];
            float sgn = (zo > 0.f) ? 1.f : ((zo < 0.f) ? -1.f : 0.f);
            float delta = (zo - gv[j]) - acc[i][j] + LAMBDA_Z * sgn;
            zn[j] = zo - INF_LR * delta;
        }
        *(float4*)(g_z + idx)     = make_float4(zn[0], zn[1], zn[2], zn[3]);
        *(float4*)(g_z + idx + 4) = make_float4(zn[4], zn[5], zn[6], zn[7]);
    }
}

// Final copy z -> d_out (avoids symbol-address plumbing; fully capturable)
__global__ void k_out(float* __restrict__ out)
{
    size_t i = (size_t)blockIdx.x * blockDim.x + threadIdx.x;
    ((float4*)out)[i] = ((const float4*)g_z)[i];
}

// ---------------------------------------------------------------------------
extern "C" void kernel_launch(void* const* d_in, const int* in_sizes, int n_in,
                              void* d_out, int out_size)
{
    const float* v      = (const float*)d_in[0];
    const float* prev_z = (const float*)d_in[1];
    const float* p      = (const float*)d_in[2];
    const float* Wr     = (const float*)d_in[3];
    const float* Win    = (const float*)d_in[4];
    const float* Wout   = (const float*)d_in[5];
    const int*   iters  = (const int*)d_in[6];

    dim3 blk(256);
    dim3 gridG(NG / BN, B_DIM / BM);   // 16 x 32
    dim3 gridP(NP / BN, B_DIM / BM);   // 8 x 32

    k_transpose<<<dim3(NG / 32, NP / 32), dim3(32, 8)>>>(Wout);
    k_gval<<<gridG, blk>>>(prev_z, Wr, v, Win);
    k_pred<<<gridP, blk>>>(Wout, p);

    for (int it = 0; it < MAX_ITERS; ++it) {
        k_update<<<gridG, blk>>>(iters, it);
        if (it + 1 < MAX_ITERS)
            k_pred<<<gridP, blk>>>(Wout, p);
    }

    k_out<<<(B_DIM * NG / 4) / 256, 256>>>((float*)d_out);
}

// round 6
// speedup vs baseline: 1.9961x; 1.9961x over previous
#include <cuda_runtime.h>
#include <cuda_bf16.h>
#include <cstdint>

// Problem dims (fixed)
#define B_DIM 4096
#define NG    2048
#define NV    128
#define NP    1024
#define MAX_ITERS 20
#define INF_LR   0.05f
#define LAMBDA_Z 1e-4f

// GEMM config: 128x128 CTA tile, BK=32 bf16, 8 warps (2 x 4), warp tile 64x32
#define BK       32
#define LDS_ROW  40                       // 32 + 8 pad (80 bytes) -> conflict-free ldmatrix
#define ROW_B    80u                      // bytes per smem row
#define TILE_B   (128u * ROW_B)           // 10240 B per tile
#define STAGE_B  (4u * TILE_B)            // Ah, Al, Bh, Bl
#define SMEM_TOTAL (2 * (int)STAGE_B)     // 81920 B

// ------------------------- scratch (device globals) -------------------------
__device__ float g_G [B_DIM * NG];
__device__ float g_z [B_DIM * NG];
__device__ __nv_bfloat16 g_zh [B_DIM * NG], g_zl [B_DIM * NG];
__device__ __nv_bfloat16 g_Eh [B_DIM * NP], g_El [B_DIM * NP];
__device__ __nv_bfloat16 g_pzh[B_DIM * NG], g_pzl[B_DIM * NG];
__device__ __nv_bfloat16 g_vh [B_DIM * NV], g_vl [B_DIM * NV];
__device__ __nv_bfloat16 g_Wrh[NG * NG],   g_Wrl[NG * NG];
__device__ __nv_bfloat16 g_Winh[NG * NV],  g_Winl[NG * NV];
__device__ __nv_bfloat16 g_Wouth[NP * NG], g_Woutl[NP * NG];
__device__ __nv_bfloat16 g_WTh[NG * NP],   g_WTl[NG * NP];

// ------------------------- low-level helpers -------------------------
__device__ __forceinline__ uint32_t smem_u32(const void* p) {
    uint32_t a;
    asm("{ .reg .u64 t; cvta.to.shared.u64 t, %1; cvt.u32.u64 %0, t; }"
        : "=r"(a) : "l"(p));
    return a;
}
__device__ __forceinline__ void cpasync16(uint32_t s, const void* g) {
    asm volatile("cp.async.cg.shared.global [%0], [%1], 16;" :: "r"(s), "l"(g));
}
#define CP_COMMIT() asm volatile("cp.async.commit_group;" ::: "memory")
#define CP_WAIT1()  asm volatile("cp.async.wait_group 1;"  ::: "memory")
#define CP_WAIT0()  asm volatile("cp.async.wait_group 0;"  ::: "memory")

__device__ __forceinline__ void ldm_x4(uint32_t* r, uint32_t addr) {
    asm volatile("ldmatrix.sync.aligned.m8n8.x4.shared.b16 {%0,%1,%2,%3}, [%4];"
        : "=r"(r[0]), "=r"(r[1]), "=r"(r[2]), "=r"(r[3]) : "r"(addr));
}
__device__ __forceinline__ void ldm_x2(uint32_t* r, uint32_t addr) {
    asm volatile("ldmatrix.sync.aligned.m8n8.x2.shared.b16 {%0,%1}, [%2];"
        : "=r"(r[0]), "=r"(r[1]) : "r"(addr));
}
__device__ __forceinline__ void mma16816(float* d, const uint32_t* a, const uint32_t* b) {
    asm volatile(
        "mma.sync.aligned.m16n8k16.row.col.f32.bf16.bf16.f32 "
        "{%0,%1,%2,%3}, {%4,%5,%6,%7}, {%8,%9}, {%0,%1,%2,%3};"
        : "+f"(d[0]), "+f"(d[1]), "+f"(d[2]), "+f"(d[3])
        : "r"(a[0]), "r"(a[1]), "r"(a[2]), "r"(a[3]), "r"(b[0]), "r"(b[1]));
}
__device__ __forceinline__ void split1(float x, __nv_bfloat16& h, __nv_bfloat16& l) {
    h = __float2bfloat16_rn(x);
    l = __float2bfloat16_rn(x - __bfloat162float(h));
}

// ------------------------- stage load (cp.async) -------------------------
// 4 tiles (Ah, Al, Bh, Bl), each 128 rows x 32 bf16 (64 B data per row).
__device__ __forceinline__ void load_stage(
    uint32_t sbase,
    const __nv_bfloat16* __restrict__ Ah, const __nv_bfloat16* __restrict__ Al,
    int lda, int rowA0,
    const __nv_bfloat16* __restrict__ Bh, const __nv_bfloat16* __restrict__ Bl,
    int ldb, int rowB0, int koff, int tid)
{
    int r0 = tid >> 2;           // 0..63
    int c0 = tid & 3;            // 16B chunk within row
    #pragma unroll
    for (int h = 0; h < 2; ++h) {
        int r = r0 + h * 64;
        uint32_t soff = (uint32_t)r * ROW_B + (uint32_t)c0 * 16u;
        size_t ga = (size_t)(rowA0 + r) * lda + koff + c0 * 8;
        cpasync16(sbase + soff,              Ah + ga);
        cpasync16(sbase + TILE_B + soff,     Al + ga);
        size_t gb = (size_t)(rowB0 + r) * ldb + koff + c0 * 8;
        cpasync16(sbase + 2u*TILE_B + soff,  Bh + gb);
        cpasync16(sbase + 3u*TILE_B + soff,  Bl + gb);
    }
}

// ------------------------- compute one BK=32 chunk -------------------------
__device__ __forceinline__ void compute_stage(
    uint32_t sbase, int warpM, int warpN, int lane, float acc[4][4][4])
{
    #pragma unroll
    for (int ks = 0; ks < 2; ++ks) {
        uint32_t ah[4][4], al[4][4];
        int arow = warpM * 64 + (lane & 15);
        int acol = ks * 16 + (lane >> 4) * 8;
        #pragma unroll
        for (int ti = 0; ti < 4; ++ti) {
            uint32_t addr = sbase + (uint32_t)(arow + ti * 16) * ROW_B
                          + (uint32_t)acol * 2u;
            ldm_x4(ah[ti], addr);
            ldm_x4(al[ti], addr + TILE_B);
        }
        #pragma unroll
        for (int tj = 0; tj < 4; ++tj) {
            uint32_t bh[2], bl[2];
            int brow = warpN * 32 + tj * 8 + (lane & 7);
            int bcol = ks * 16 + ((lane >> 3) & 1) * 8;
            uint32_t baddr = sbase + 2u*TILE_B + (uint32_t)brow * ROW_B
                           + (uint32_t)bcol * 2u;
            ldm_x2(bh, baddr);
            ldm_x2(bl, baddr + TILE_B);
            #pragma unroll
            for (int ti = 0; ti < 4; ++ti) {
                mma16816(acc[ti][tj], ah[ti], bh);   // hi * hi
                mma16816(acc[ti][tj], ah[ti], bl);   // hi * lo
                mma16816(acc[ti][tj], al[ti], bh);   // lo * hi
            }
        }
    }
}

// ------------------------- pipelined mainloop -------------------------
__device__ __forceinline__ void gemm_mainloop(
    float acc[4][4][4],
    const __nv_bfloat16* __restrict__ Ah, const __nv_bfloat16* __restrict__ Al,
    int lda, int rowA0,
    const __nv_bfloat16* __restrict__ Bh, const __nv_bfloat16* __restrict__ Bl,
    int ldb, int rowB0, int kTotal, uint32_t sb, int tid)
{
    int nC   = kTotal / BK;
    int lane = tid & 31, warp = tid >> 5;
    int warpM = warp >> 2, warpN = warp & 3;   // 2 x 4

    load_stage(sb, Ah, Al, lda, rowA0, Bh, Bl, ldb, rowB0, 0, tid);
    CP_COMMIT();
    for (int c = 0; c < nC; ++c) {
        if (c + 1 < nC) {
            load_stage(sb + (uint32_t)((c + 1) & 1) * STAGE_B,
                       Ah, Al, lda, rowA0, Bh, Bl, ldb, rowB0, (c + 1) * BK, tid);
            CP_COMMIT();
            CP_WAIT1();
        } else {
            CP_WAIT0();
        }
        __syncthreads();
        compute_stage(sb + (uint32_t)(c & 1) * STAGE_B, warpM, warpN, lane, acc);
        __syncthreads();
    }
}

// ------------------------- conversion kernels -------------------------
__global__ void k_split(const float* __restrict__ x, __nv_bfloat16* __restrict__ h,
                        __nv_bfloat16* __restrict__ l, int n4)
{
    int i = blockIdx.x * blockDim.x + threadIdx.x;
    if (i >= n4) return;
    float4 v = ((const float4*)x)[i];
    __nv_bfloat16 h0,h1,h2,h3, l0,l1,l2,l3;
    split1(v.x, h0, l0); split1(v.y, h1, l1);
    split1(v.z, h2, l2); split1(v.w, h3, l3);
    ((__nv_bfloat162*)h)[2*i]   = __nv_bfloat162(h0, h1);
    ((__nv_bfloat162*)h)[2*i+1] = __nv_bfloat162(h2, h3);
    ((__nv_bfloat162*)l)[2*i]   = __nv_bfloat162(l0, l1);
    ((__nv_bfloat162*)l)[2*i+1] = __nv_bfloat162(l2, l3);
}

__global__ void k_transpose_split(const float* __restrict__ Wout)
{
    __shared__ float tile[32][33];
    int x = blockIdx.x * 32 + threadIdx.x;   // g
    int y = blockIdx.y * 32 + threadIdx.y;   // p
    #pragma unroll
    for (int i = 0; i < 32; i += 8)
        tile[threadIdx.y + i][threadIdx.x] = Wout[(size_t)(y + i) * NG + x];
    __syncthreads();
    int xo = blockIdx.y * 32 + threadIdx.x;  // p
    int yo = blockIdx.x * 32 + threadIdx.y;  // g
    #pragma unroll
    for (int i = 0; i < 32; i += 8) {
        float v = tile[threadIdx.x][threadIdx.y + i];
        __nv_bfloat16 h, l; split1(v, h, l);
        g_WTh[(size_t)(yo + i) * NP + xo] = h;
        g_WTl[(size_t)(yo + i) * NP + xo] = l;
    }
}

// ------------------------- GEMM kernels -------------------------
// K1: G = tanh(prev_z @ Wr^T + v @ Win^T); z = G; split z -> bf16 hi/lo
__global__ __launch_bounds__(256, 1) void k_gval()
{
    extern __shared__ char smem[];
    uint32_t sb = smem_u32(smem);
    int tid = threadIdx.x;
    int lane = tid & 31, warp = tid >> 5;
    int warpM = warp >> 2, warpN = warp & 3;
    int rowA0 = blockIdx.y * 128, colB0 = blockIdx.x * 128;

    float acc[4][4][4];
    #pragma unroll
    for (int a = 0; a < 4; ++a)
        #pragma unroll
        for (int b = 0; b < 4; ++b)
            #pragma unroll
            for (int c = 0; c < 4; ++c) acc[a][b][c] = 0.f;

    gemm_mainloop(acc, g_pzh, g_pzl, NG, rowA0, g_Wrh,  g_Wrl,  NG, colB0, NG, sb, tid);
    gemm_mainloop(acc, g_vh,  g_vl,  NV, rowA0, g_Winh, g_Winl, NV, colB0, NV, sb, tid);

    #pragma unroll
    for (int ti = 0; ti < 4; ++ti) {
        int rbase = rowA0 + warpM * 64 + ti * 16 + (lane >> 2);
        #pragma unroll
        for (int tj = 0; tj < 4; ++tj) {
            int cc = colB0 + warpN * 32 + tj * 8 + (lane & 3) * 2;
            #pragma unroll
            for (int h = 0; h < 2; ++h) {
                int row = rbase + h * 8;
                float t0 = tanhf(acc[ti][tj][2*h]);
                float t1 = tanhf(acc[ti][tj][2*h+1]);
                size_t idx = (size_t)row * NG + cc;
                *(float2*)(g_G + idx) = make_float2(t0, t1);
                *(float2*)(g_z + idx) = make_float2(t0, t1);
                __nv_bfloat16 h0,h1,l0,l1;
                split1(t0, h0, l0); split1(t1, h1, l1);
                *(__nv_bfloat162*)(g_zh + idx) = __nv_bfloat162(h0, h1);
                *(__nv_bfloat162*)(g_zl + idx) = __nv_bfloat162(l0, l1);
            }
        }
    }
}

// K2: pred = tanh(z @ Wout^T); E = (1-pred^2)(p-pred); split E -> bf16 hi/lo
__global__ __launch_bounds__(256, 1) void k_pred(const float* __restrict__ p)
{
    extern __shared__ char smem[];
    uint32_t sb = smem_u32(smem);
    int tid = threadIdx.x;
    int lane = tid & 31, warp = tid >> 5;
    int warpM = warp >> 2, warpN = warp & 3;
    int rowA0 = blockIdx.y * 128, colB0 = blockIdx.x * 128;

    float acc[4][4][4];
    #pragma unroll
    for (int a = 0; a < 4; ++a)
        #pragma unroll
        for (int b = 0; b < 4; ++b)
            #pragma unroll
            for (int c = 0; c < 4; ++c) acc[a][b][c] = 0.f;

    gemm_mainloop(acc, g_zh, g_zl, NG, rowA0, g_Wouth, g_Woutl, NG, colB0, NG, sb, tid);

    #pragma unroll
    for (int ti = 0; ti < 4; ++ti) {
        int rbase = rowA0 + warpM * 64 + ti * 16 + (lane >> 2);
        #pragma unroll
        for (int tj = 0; tj < 4; ++tj) {
            int cc = colB0 + warpN * 32 + tj * 8 + (lane & 3) * 2;
            #pragma unroll
            for (int h = 0; h < 2; ++h) {
                int row = rbase + h * 8;
                size_t idx = (size_t)row * NP + cc;
                float2 pv = *(const float2*)(p + idx);
                float pr0 = tanhf(acc[ti][tj][2*h]);
                float pr1 = tanhf(acc[ti][tj][2*h+1]);
                float e0 = (1.0f - pr0*pr0) * (pv.x - pr0);
                float e1 = (1.0f - pr1*pr1) * (pv.y - pr1);
                __nv_bfloat16 h0,h1,l0,l1;
                split1(e0, h0, l0); split1(e1, h1, l1);
                *(__nv_bfloat162*)(g_Eh + idx) = __nv_bfloat162(h0, h1);
                *(__nv_bfloat162*)(g_El + idx) = __nv_bfloat162(l0, l1);
            }
        }
    }
}

// K3: U = E @ WT^T; z -= lr*((z-G) - U + lambda*sign(z)); re-split z
__global__ __launch_bounds__(256, 1) void k_update(const int* __restrict__ n_iters, int iter)
{
    if (iter >= *n_iters) return;
    extern __shared__ char smem[];
    uint32_t sb = smem_u32(smem);
    int tid = threadIdx.x;
    int lane = tid & 31, warp = tid >> 5;
    int warpM = warp >> 2, warpN = warp & 3;
    int rowA0 = blockIdx.y * 128, colB0 = blockIdx.x * 128;

    float acc[4][4][4];
    #pragma unroll
    for (int a = 0; a < 4; ++a)
        #pragma unroll
        for (int b = 0; b < 4; ++b)
            #pragma unroll
            for (int c = 0; c < 4; ++c) acc[a][b][c] = 0.f;

    gemm_mainloop(acc, g_Eh, g_El, NP, rowA0, g_WTh, g_WTl, NP, colB0, NP, sb, tid);

    #pragma unroll
    for (int ti = 0; ti < 4; ++ti) {
        int rbase = rowA0 + warpM * 64 + ti * 16 + (lane >> 2);
        #pragma unroll
        for (int tj = 0; tj < 4; ++tj) {
            int cc = colB0 + warpN * 32 + tj * 8 + (lane & 3) * 2;
            #pragma unroll
            for (int h = 0; h < 2; ++h) {
                int row = rbase + h * 8;
                size_t idx = (size_t)row * NG + cc;
                float2 zv = *(const float2*)(g_z + idx);
                float2 gv = *(const float2*)(g_G + idx);
                float u0 = acc[ti][tj][2*h], u1 = acc[ti][tj][2*h+1];
                float s0 = (zv.x > 0.f) ? 1.f : ((zv.x < 0.f) ? -1.f : 0.f);
                float s1 = (zv.y > 0.f) ? 1.f : ((zv.y < 0.f) ? -1.f : 0.f);
                float zn0 = zv.x - INF_LR * ((zv.x - gv.x) - u0 + LAMBDA_Z * s0);
                float zn1 = zv.y - INF_LR * ((zv.y - gv.y) - u1 + LAMBDA_Z * s1);
                *(float2*)(g_z + idx) = make_float2(zn0, zn1);
                __nv_bfloat16 h0,h1,l0,l1;
                split1(zn0, h0, l0); split1(zn1, h1, l1);
                *(__nv_bfloat162*)(g_zh + idx) = __nv_bfloat162(h0, h1);
                *(__nv_bfloat162*)(g_zl + idx) = __nv_bfloat162(l0, l1);
            }
        }
    }
}

__global__ void k_out(float* __restrict__ out)
{
    size_t i = (size_t)blockIdx.x * blockDim.x + threadIdx.x;
    ((float4*)out)[i] = ((const float4*)g_z)[i];
}

// ---------------------------------------------------------------------------
extern "C" void kernel_launch(void* const* d_in, const int* in_sizes, int n_in,
                              void* d_out, int out_size)
{
    const float* v      = (const float*)d_in[0];
    const float* prev_z = (const float*)d_in[1];
    const float* p      = (const float*)d_in[2];
    const float* Wr     = (const float*)d_in[3];
    const float* Win    = (const float*)d_in[4];
    const float* Wout   = (const float*)d_in[5];
    const int*   iters  = (const int*)d_in[6];

    static bool attr_done = false;
    if (!attr_done) {
        cudaFuncSetAttribute(k_gval,   cudaFuncAttributeMaxDynamicSharedMemorySize, SMEM_TOTAL);
        cudaFuncSetAttribute(k_pred,   cudaFuncAttributeMaxDynamicSharedMemorySize, SMEM_TOTAL);
        cudaFuncSetAttribute(k_update, cudaFuncAttributeMaxDynamicSharedMemorySize, SMEM_TOTAL);
        attr_done = true;
    }

    __nv_bfloat16 *vh, *vl, *pzh, *pzl, *wrh, *wrl, *winh, *winl, *woh, *wol;
    cudaGetSymbolAddress((void**)&vh,  g_vh);  cudaGetSymbolAddress((void**)&vl,  g_vl);
    cudaGetSymbolAddress((void**)&pzh, g_pzh); cudaGetSymbolAddress((void**)&pzl, g_pzl);
    cudaGetSymbolAddress((void**)&wrh, g_Wrh); cudaGetSymbolAddress((void**)&wrl, g_Wrl);
    cudaGetSymbolAddress((void**)&winh,g_Winh);cudaGetSymbolAddress((void**)&winl,g_Winl);
    cudaGetSymbolAddress((void**)&woh, g_Wouth);cudaGetSymbolAddress((void**)&wol, g_Woutl);

    auto split = [](const float* x, __nv_bfloat16* h, __nv_bfloat16* l, int n) {
        int n4 = n / 4;
        k_split<<<(n4 + 255) / 256, 256>>>(x, h, l, n4);
    };
    split(v,      vh,  vl,  B_DIM * NV);
    split(prev_z, pzh, pzl, B_DIM * NG);
    split(Wr,     wrh, wrl, NG * NG);
    split(Win,    winh,winl,NG * NV);
    split(Wout,   woh, wol, NP * NG);
    k_transpose_split<<<dim3(NG / 32, NP / 32), dim3(32, 8)>>>(Wout);

    dim3 blk(256);
    dim3 gridG(NG / 128, B_DIM / 128);   // 16 x 32
    dim3 gridP(NP / 128, B_DIM / 128);   // 8 x 32

    k_gval<<<gridG, blk, SMEM_TOTAL>>>();
    k_pred<<<gridP, blk, SMEM_TOTAL>>>(p);
    for (int it = 0; it < MAX_ITERS; ++it) {
        k_update<<<gridG, blk, SMEM_TOTAL>>>(iters, it);
        if (it + 1 < MAX_ITERS)
            k_pred<<<gridP, blk, SMEM_TOTAL>>>(p);
    }
    k_out<<<(B_DIM * NG / 4) / 256, 256>>>((float*)d_out);
}

// round 7
// speedup vs baseline: 2.4642x; 1.2345x over previous
#include <cuda_runtime.h>
#include <cuda_bf16.h>
#include <cstdint>

// Problem dims (fixed)
#define B_DIM 4096
#define NG    2048
#define NV    128
#define NP    1024
#define MAX_ITERS 20
#define INF_LR   0.05f
#define LAMBDA_Z 1e-4f

// GEMM config: 128x128 CTA tile, BK=32 bf16, 8 warps (2 x 4), warp tile 64x32
#define BK       32
#define ROW_B    80u                      // 32*2 + 16 pad bytes -> conflict-free ldmatrix
#define TILE_B   (128u * ROW_B)           // 10240 B per tile
#define STAGE_B  (4u * TILE_B)            // Ah, Al, Bh, Bl
#define SMEM_TOTAL (2 * (int)STAGE_B)     // 81920 B (2 stages) -> 2 CTAs/SM

// ------------------------- scratch (device globals) -------------------------
__device__ float g_G [B_DIM * NG];
__device__ float g_z [B_DIM * NG];
__device__ __nv_bfloat16 g_zh [B_DIM * NG], g_zl [B_DIM * NG];
__device__ __nv_bfloat16 g_Eh [B_DIM * NP], g_El [B_DIM * NP];
__device__ __nv_bfloat16 g_pzh[B_DIM * NG], g_pzl[B_DIM * NG];
__device__ __nv_bfloat16 g_vh [B_DIM * NV], g_vl [B_DIM * NV];
__device__ __nv_bfloat16 g_Wrh[NG * NG],   g_Wrl[NG * NG];
__device__ __nv_bfloat16 g_Winh[NG * NV],  g_Winl[NG * NV];
__device__ __nv_bfloat16 g_Wouth[NP * NG], g_Woutl[NP * NG];
__device__ __nv_bfloat16 g_WTh[NG * NP],   g_WTl[NG * NP];

// ------------------------- low-level helpers -------------------------
__device__ __forceinline__ uint32_t smem_u32(const void* p) {
    uint32_t a;
    asm("{ .reg .u64 t; cvta.to.shared.u64 t, %1; cvt.u32.u64 %0, t; }"
        : "=r"(a) : "l"(p));
    return a;
}
__device__ __forceinline__ void cpasync16(uint32_t s, const void* g) {
    asm volatile("cp.async.cg.shared.global [%0], [%1], 16;" :: "r"(s), "l"(g));
}
#define CP_COMMIT() asm volatile("cp.async.commit_group;" ::: "memory")
#define CP_WAIT0()  asm volatile("cp.async.wait_group 0;"  ::: "memory")

__device__ __forceinline__ void ldm_x4(uint32_t* r, uint32_t addr) {
    asm volatile("ldmatrix.sync.aligned.m8n8.x4.shared.b16 {%0,%1,%2,%3}, [%4];"
        : "=r"(r[0]), "=r"(r[1]), "=r"(r[2]), "=r"(r[3]) : "r"(addr));
}
__device__ __forceinline__ void mma16816(float* d, const uint32_t* a, const uint32_t* b) {
    asm volatile(
        "mma.sync.aligned.m16n8k16.row.col.f32.bf16.bf16.f32 "
        "{%0,%1,%2,%3}, {%4,%5,%6,%7}, {%8,%9}, {%0,%1,%2,%3};"
        : "+f"(d[0]), "+f"(d[1]), "+f"(d[2]), "+f"(d[3])
        : "r"(a[0]), "r"(a[1]), "r"(a[2]), "r"(a[3]), "r"(b[0]), "r"(b[1]));
}
__device__ __forceinline__ void split1(float x, __nv_bfloat16& h, __nv_bfloat16& l) {
    h = __float2bfloat16_rn(x);
    l = __float2bfloat16_rn(x - __bfloat162float(h));
}

// ------------------------- stage load (cp.async) -------------------------
// 4 tiles (Ah, Al, Bh, Bl), each 128 rows x 32 bf16 (64 B data per row).
__device__ __forceinline__ void load_stage(
    uint32_t sbase,
    const __nv_bfloat16* __restrict__ Ah, const __nv_bfloat16* __restrict__ Al,
    int lda, int rowA0,
    const __nv_bfloat16* __restrict__ Bh, const __nv_bfloat16* __restrict__ Bl,
    int ldb, int rowB0, int koff, int tid)
{
    int r0 = tid >> 2;           // 0..63
    int c0 = tid & 3;            // 16B chunk within row
    #pragma unroll
    for (int h = 0; h < 2; ++h) {
        int r = r0 + h * 64;
        uint32_t soff = (uint32_t)r * ROW_B + (uint32_t)c0 * 16u;
        size_t ga = (size_t)(rowA0 + r) * lda + koff + c0 * 8;
        cpasync16(sbase + soff,              Ah + ga);
        cpasync16(sbase + TILE_B + soff,     Al + ga);
        size_t gb = (size_t)(rowB0 + r) * ldb + koff + c0 * 8;
        cpasync16(sbase + 2u*TILE_B + soff,  Bh + gb);
        cpasync16(sbase + 3u*TILE_B + soff,  Bl + gb);
    }
}

// ------------------------- compute one BK=32 chunk -------------------------
__device__ __forceinline__ void compute_stage(
    uint32_t sbase, int warpM, int warpN, int lane, float acc[4][4][4])
{
    #pragma unroll
    for (int ks = 0; ks < 2; ++ks) {
        uint32_t ah[4][4], al[4][4];
        int arow = warpM * 64 + (lane & 15);
        int acol = ks * 16 + (lane >> 4) * 8;
        #pragma unroll
        for (int ti = 0; ti < 4; ++ti) {
            uint32_t addr = sbase + (uint32_t)(arow + ti * 16) * ROW_B
                          + (uint32_t)acol * 2u;
            ldm_x4(ah[ti], addr);
            ldm_x4(al[ti], addr + TILE_B);
        }
        // B fragments: one x4 covers two n-tiles (tj pair) x both k-halves
        int mi    = lane >> 3;        // matrix index 0..3
        int tjo   = mi >> 1;          // 0/1 within pair
        int khalf = mi & 1;           // k rows 0-7 / 8-15
        #pragma unroll
        for (int tp = 0; tp < 2; ++tp) {
            uint32_t bh[4], bl[4];
            int brow = warpN * 32 + (tp * 2 + tjo) * 8 + (lane & 7);
            int bcol = ks * 16 + khalf * 8;
            uint32_t baddr = sbase + 2u*TILE_B + (uint32_t)brow * ROW_B
                           + (uint32_t)bcol * 2u;
            ldm_x4(bh, baddr);
            ldm_x4(bl, baddr + TILE_B);
            #pragma unroll
            for (int ti = 0; ti < 4; ++ti) {
                mma16816(acc[ti][tp*2+0], ah[ti], bh + 0);
                mma16816(acc[ti][tp*2+0], ah[ti], bl + 0);
                mma16816(acc[ti][tp*2+0], al[ti], bh + 0);
                mma16816(acc[ti][tp*2+1], ah[ti], bh + 2);
                mma16816(acc[ti][tp*2+1], ah[ti], bl + 2);
                mma16816(acc[ti][tp*2+1], al[ti], bh + 2);
            }
        }
    }
}

// ------------------------- pipelined mainloop (single sync/chunk) ----------
__device__ __forceinline__ void gemm_mainloop(
    float acc[4][4][4],
    const __nv_bfloat16* __restrict__ Ah, const __nv_bfloat16* __restrict__ Al,
    int lda, int rowA0,
    const __nv_bfloat16* __restrict__ Bh, const __nv_bfloat16* __restrict__ Bl,
    int ldb, int rowB0, int kTotal, uint32_t sb, int tid)
{
    int nC   = kTotal / BK;
    int lane = tid & 31, warp = tid >> 5;
    int warpM = warp >> 2, warpN = warp & 3;   // 2 x 4

    load_stage(sb, Ah, Al, lda, rowA0, Bh, Bl, ldb, rowB0, 0, tid);
    CP_COMMIT();
    for (int c = 0; c < nC; ++c) {
        CP_WAIT0();          // data for chunk c landed (issued last iteration)
        __syncthreads();     // all warps done with the buffer we're about to refill
        if (c + 1 < nC) {
            load_stage(sb + (uint32_t)((c + 1) & 1) * STAGE_B,
                       Ah, Al, lda, rowA0, Bh, Bl, ldb, rowB0, (c + 1) * BK, tid);
            CP_COMMIT();
        }
        compute_stage(sb + (uint32_t)(c & 1) * STAGE_B, warpM, warpN, lane, acc);
    }
}

// ------------------------- conversion kernels -------------------------
__global__ void k_split(const float* __restrict__ x, __nv_bfloat16* __restrict__ h,
                        __nv_bfloat16* __restrict__ l, int n4)
{
    int i = blockIdx.x * blockDim.x + threadIdx.x;
    if (i >= n4) return;
    float4 v = ((const float4*)x)[i];
    __nv_bfloat16 h0,h1,h2,h3, l0,l1,l2,l3;
    split1(v.x, h0, l0); split1(v.y, h1, l1);
    split1(v.z, h2, l2); split1(v.w, h3, l3);
    ((__nv_bfloat162*)h)[2*i]   = __nv_bfloat162(h0, h1);
    ((__nv_bfloat162*)h)[2*i+1] = __nv_bfloat162(h2, h3);
    ((__nv_bfloat162*)l)[2*i]   = __nv_bfloat162(l0, l1);
    ((__nv_bfloat162*)l)[2*i+1] = __nv_bfloat162(l2, l3);
}

__global__ void k_transpose_split(const float* __restrict__ Wout)
{
    __shared__ float tile[32][33];
    int x = blockIdx.x * 32 + threadIdx.x;   // g
    int y = blockIdx.y * 32 + threadIdx.y;   // p
    #pragma unroll
    for (int i = 0; i < 32; i += 8)
        tile[threadIdx.y + i][threadIdx.x] = Wout[(size_t)(y + i) * NG + x];
    __syncthreads();
    int xo = blockIdx.y * 32 + threadIdx.x;  // p
    int yo = blockIdx.x * 32 + threadIdx.y;  // g
    #pragma unroll
    for (int i = 0; i < 32; i += 8) {
        float v = tile[threadIdx.x][threadIdx.y + i];
        __nv_bfloat16 h, l; split1(v, h, l);
        g_WTh[(size_t)(yo + i) * NP + xo] = h;
        g_WTl[(size_t)(yo + i) * NP + xo] = l;
    }
}

// ------------------------- GEMM kernels -------------------------
// K1: G = tanh(prev_z @ Wr^T + v @ Win^T); z = G; split z -> bf16 hi/lo
__global__ __launch_bounds__(256, 2) void k_gval()
{
    extern __shared__ char smem[];
    uint32_t sb = smem_u32(smem);
    int tid = threadIdx.x;
    int lane = tid & 31, warp = tid >> 5;
    int warpM = warp >> 2, warpN = warp & 3;
    int rowA0 = blockIdx.y * 128, colB0 = blockIdx.x * 128;

    float acc[4][4][4];
    #pragma unroll
    for (int a = 0; a < 4; ++a)
        #pragma unroll
        for (int b = 0; b < 4; ++b)
            #pragma unroll
            for (int c = 0; c < 4; ++c) acc[a][b][c] = 0.f;

    gemm_mainloop(acc, g_pzh, g_pzl, NG, rowA0, g_Wrh,  g_Wrl,  NG, colB0, NG, sb, tid);
    gemm_mainloop(acc, g_vh,  g_vl,  NV, rowA0, g_Winh, g_Winl, NV, colB0, NV, sb, tid);

    #pragma unroll
    for (int ti = 0; ti < 4; ++ti) {
        int rbase = rowA0 + warpM * 64 + ti * 16 + (lane >> 2);
        #pragma unroll
        for (int tj = 0; tj < 4; ++tj) {
            int cc = colB0 + warpN * 32 + tj * 8 + (lane & 3) * 2;
            #pragma unroll
            for (int h = 0; h < 2; ++h) {
                int row = rbase + h * 8;
                float t0 = tanhf(acc[ti][tj][2*h]);
                float t1 = tanhf(acc[ti][tj][2*h+1]);
                size_t idx = (size_t)row * NG + cc;
                *(float2*)(g_G + idx) = make_float2(t0, t1);
                *(float2*)(g_z + idx) = make_float2(t0, t1);
                __nv_bfloat16 h0,h1,l0,l1;
                split1(t0, h0, l0); split1(t1, h1, l1);
                *(__nv_bfloat162*)(g_zh + idx) = __nv_bfloat162(h0, h1);
                *(__nv_bfloat162*)(g_zl + idx) = __nv_bfloat162(l0, l1);
            }
        }
    }
}

// K2: pred = tanh(z @ Wout^T); E = (1-pred^2)(p-pred); split E -> bf16 hi/lo
__global__ __launch_bounds__(256, 2) void k_pred(const float* __restrict__ p)
{
    extern __shared__ char smem[];
    uint32_t sb = smem_u32(smem);
    int tid = threadIdx.x;
    int lane = tid & 31, warp = tid >> 5;
    int warpM = warp >> 2, warpN = warp & 3;
    int rowA0 = blockIdx.y * 128, colB0 = blockIdx.x * 128;

    float acc[4][4][4];
    #pragma unroll
    for (int a = 0; a < 4; ++a)
        #pragma unroll
        for (int b = 0; b < 4; ++b)
            #pragma unroll
            for (int c = 0; c < 4; ++c) acc[a][b][c] = 0.f;

    gemm_mainloop(acc, g_zh, g_zl, NG, rowA0, g_Wouth, g_Woutl, NG, colB0, NG, sb, tid);

    #pragma unroll
    for (int ti = 0; ti < 4; ++ti) {
        int rbase = rowA0 + warpM * 64 + ti * 16 + (lane >> 2);
        #pragma unroll
        for (int tj = 0; tj < 4; ++tj) {
            int cc = colB0 + warpN * 32 + tj * 8 + (lane & 3) * 2;
            #pragma unroll
            for (int h = 0; h < 2; ++h) {
                int row = rbase + h * 8;
                size_t idx = (size_t)row * NP + cc;
                float2 pv = *(const float2*)(p + idx);
                float pr0 = tanhf(acc[ti][tj][2*h]);
                float pr1 = tanhf(acc[ti][tj][2*h+1]);
                float e0 = (1.0f - pr0*pr0) * (pv.x - pr0);
                float e1 = (1.0f - pr1*pr1) * (pv.y - pr1);
                __nv_bfloat16 h0,h1,l0,l1;
                split1(e0, h0, l0); split1(e1, h1, l1);
                *(__nv_bfloat162*)(g_Eh + idx) = __nv_bfloat162(h0, h1);
                *(__nv_bfloat162*)(g_El + idx) = __nv_bfloat162(l0, l1);
            }
        }
    }
}

// K3: U = E @ WT^T; z -= lr*((z-G) - U + lambda*sign(z)); re-split z
__global__ __launch_bounds__(256, 2) void k_update(const int* __restrict__ n_iters, int iter)
{
    if (iter >= *n_iters) return;
    extern __shared__ char smem[];
    uint32_t sb = smem_u32(smem);
    int tid = threadIdx.x;
    int lane = tid & 31, warp = tid >> 5;
    int warpM = warp >> 2, warpN = warp & 3;
    int rowA0 = blockIdx.y * 128, colB0 = blockIdx.x * 128;

    float acc[4][4][4];
    #pragma unroll
    for (int a = 0; a < 4; ++a)
        #pragma unroll
        for (int b = 0; b < 4; ++b)
            #pragma unroll
            for (int c = 0; c < 4; ++c) acc[a][b][c] = 0.f;

    gemm_mainloop(acc, g_Eh, g_El, NP, rowA0, g_WTh, g_WTl, NP, colB0, NP, sb, tid);

    #pragma unroll
    for (int ti = 0; ti < 4; ++ti) {
        int rbase = rowA0 + warpM * 64 + ti * 16 + (lane >> 2);
        #pragma unroll
        for (int tj = 0; tj < 4; ++tj) {
            int cc = colB0 + warpN * 32 + tj * 8 + (lane & 3) * 2;
            #pragma unroll
            for (int h = 0; h < 2; ++h) {
                int row = rbase + h * 8;
                size_t idx = (size_t)row * NG + cc;
                float2 zv = *(const float2*)(g_z + idx);
                float2 gv = *(const float2*)(g_G + idx);
                float u0 = acc[ti][tj][2*h], u1 = acc[ti][tj][2*h+1];
                float s0 = (zv.x > 0.f) ? 1.f : ((zv.x < 0.f) ? -1.f : 0.f);
                float s1 = (zv.y > 0.f) ? 1.f : ((zv.y < 0.f) ? -1.f : 0.f);
                float zn0 = zv.x - INF_LR * ((zv.x - gv.x) - u0 + LAMBDA_Z * s0);
                float zn1 = zv.y - INF_LR * ((zv.y - gv.y) - u1 + LAMBDA_Z * s1);
                *(float2*)(g_z + idx) = make_float2(zn0, zn1);
                __nv_bfloat16 h0,h1,l0,l1;
                split1(zn0, h0, l0); split1(zn1, h1, l1);
                *(__nv_bfloat162*)(g_zh + idx) = __nv_bfloat162(h0, h1);
                *(__nv_bfloat162*)(g_zl + idx) = __nv_bfloat162(l0, l1);
            }
        }
    }
}

__global__ void k_out(float* __restrict__ out)
{
    size_t i = (size_t)blockIdx.x * blockDim.x + threadIdx.x;
    ((float4*)out)[i] = ((const float4*)g_z)[i];
}

// ---------------------------------------------------------------------------
extern "C" void kernel_launch(void* const* d_in, const int* in_sizes, int n_in,
                              void* d_out, int out_size)
{
    const float* v      = (const float*)d_in[0];
    const float* prev_z = (const float*)d_in[1];
    const float* p      = (const float*)d_in[2];
    const float* Wr     = (const float*)d_in[3];
    const float* Win    = (const float*)d_in[4];
    const float* Wout   = (const float*)d_in[5];
    const int*   iters  = (const int*)d_in[6];

    static bool attr_done = false;
    if (!attr_done) {
        cudaFuncSetAttribute(k_gval,   cudaFuncAttributeMaxDynamicSharedMemorySize, SMEM_TOTAL);
        cudaFuncSetAttribute(k_pred,   cudaFuncAttributeMaxDynamicSharedMemorySize, SMEM_TOTAL);
        cudaFuncSetAttribute(k_update, cudaFuncAttributeMaxDynamicSharedMemorySize, SMEM_TOTAL);
        attr_done = true;
    }

    __nv_bfloat16 *vh, *vl, *pzh, *pzl, *wrh, *wrl, *winh, *winl, *woh, *wol;
    cudaGetSymbolAddress((void**)&vh,  g_vh);  cudaGetSymbolAddress((void**)&vl,  g_vl);
    cudaGetSymbolAddress((void**)&pzh, g_pzh); cudaGetSymbolAddress((void**)&pzl, g_pzl);
    cudaGetSymbolAddress((void**)&wrh, g_Wrh); cudaGetSymbolAddress((void**)&wrl, g_Wrl);
    cudaGetSymbolAddress((void**)&winh,g_Winh);cudaGetSymbolAddress((void**)&winl,g_Winl);
    cudaGetSymbolAddress((void**)&woh, g_Wouth);cudaGetSymbolAddress((void**)&wol, g_Woutl);

    auto split = [](const float* x, __nv_bfloat16* h, __nv_bfloat16* l, int n) {
        int n4 = n / 4;
        k_split<<<(n4 + 255) / 256, 256>>>(x, h, l, n4);
    };
    split(v,      vh,  vl,  B_DIM * NV);
    split(prev_z, pzh, pzl, B_DIM * NG);
    split(Wr,     wrh, wrl, NG * NG);
    split(Win,    winh,winl,NG * NV);
    split(Wout,   woh, wol, NP * NG);
    k_transpose_split<<<dim3(NG / 32, NP / 32), dim3(32, 8)>>>(Wout);

    dim3 blk(256);
    dim3 gridG(NG / 128, B_DIM / 128);   // 16 x 32
    dim3 gridP(NP / 128, B_DIM / 128);   // 8 x 32

    k_gval<<<gridG, blk, SMEM_TOTAL>>>();
    k_pred<<<gridP, blk, SMEM_TOTAL>>>(p);
    for (int it = 0; it < MAX_ITERS; ++it) {
        k_update<<<gridG, blk, SMEM_TOTAL>>>(iters, it);
        if (it + 1 < MAX_ITERS)
            k_pred<<<gridP, blk, SMEM_TOTAL>>>(p);
    }
    k_out<<<(B_DIM * NG / 4) / 256, 256>>>((float*)d_out);
}

// round 10
// speedup vs baseline: 2.5455x; 1.0330x over previous
#include <cuda_runtime.h>
#include <cuda_bf16.h>
#include <cstdint>

// Problem dims (fixed)
#define B_DIM 4096
#define NG    2048
#define NV    128
#define NP    1024
#define MAX_ITERS 20
#define INF_LR   0.05f
#define LAMBDA_Z 1e-4f

// GEMM config: 128x128 CTA tile, BK=32 bf16, 8 warps (2 x 4), warp tile 64x32
#define BK       32
#define ROW_B    80u                      // 64B data + 16B pad -> conflict-free ldmatrix
#define TILE_B   (128u * ROW_B)           // 10240 B per tile
#define STAGE_B  (4u * TILE_B)            // Ah, Al, Bh, Bl
#define SMEM_TOTAL (2 * (int)STAGE_B)     // 81920 B (2 stages) -> 2 CTAs/SM

// ------------------------- scratch (device globals) -------------------------
__device__ float g_G [B_DIM * NG];
__device__ float g_z [B_DIM * NG];
__device__ __nv_bfloat16 g_zh [B_DIM * NG], g_zl [B_DIM * NG];
__device__ __nv_bfloat16 g_Eh [B_DIM * NP], g_El [B_DIM * NP];
__device__ __nv_bfloat16 g_pzh[B_DIM * NG], g_pzl[B_DIM * NG];
__device__ __nv_bfloat16 g_vh [B_DIM * NV], g_vl [B_DIM * NV];
__device__ __nv_bfloat16 g_Wrh[NG * NG],   g_Wrl[NG * NG];
__device__ __nv_bfloat16 g_Winh[NG * NV],  g_Winl[NG * NV];
__device__ __nv_bfloat16 g_Wouth[NP * NG], g_Woutl[NP * NG];
__device__ __nv_bfloat16 g_WTh[NG * NP],   g_WTl[NG * NP];

// ------------------------- low-level helpers -------------------------
__device__ __forceinline__ uint32_t smem_u32(const void* p) {
    uint32_t a;
    asm("{ .reg .u64 t; cvta.to.shared.u64 t, %1; cvt.u32.u64 %0, t; }"
        : "=r"(a) : "l"(p));
    return a;
}
__device__ __forceinline__ void cpasync16(uint32_t s, const void* g) {
    asm volatile("cp.async.cg.shared.global [%0], [%1], 16;" :: "r"(s), "l"(g));
}
#define CP_COMMIT() asm volatile("cp.async.commit_group;" ::: "memory")
#define CP_WAIT0()  asm volatile("cp.async.wait_group 0;"  ::: "memory")

__device__ __forceinline__ void ldm_x4(uint32_t* r, uint32_t addr) {
    asm volatile("ldmatrix.sync.aligned.m8n8.x4.shared.b16 {%0,%1,%2,%3}, [%4];"
        : "=r"(r[0]), "=r"(r[1]), "=r"(r[2]), "=r"(r[3]) : "r"(addr));
}
__device__ __forceinline__ void mma16816(float* d, const uint32_t* a, const uint32_t* b) {
    asm volatile(
        "mma.sync.aligned.m16n8k16.row.col.f32.bf16.bf16.f32 "
        "{%0,%1,%2,%3}, {%4,%5,%6,%7}, {%8,%9}, {%0,%1,%2,%3};"
        : "+f"(d[0]), "+f"(d[1]), "+f"(d[2]), "+f"(d[3])
        : "r"(a[0]), "r"(a[1]), "r"(a[2]), "r"(a[3]), "r"(b[0]), "r"(b[1]));
}
__device__ __forceinline__ void split1(float x, __nv_bfloat16& h, __nv_bfloat16& l) {
    h = __float2bfloat16_rn(x);
    l = __float2bfloat16_rn(x - __bfloat162float(h));
}

// ------------------------- stage load (cp.async) -------------------------
// 4 tiles (Ah, Al, Bh, Bl), each 128 rows x 32 bf16 (64 B data per row).
__device__ __forceinline__ void load_stage(
    uint32_t sbase,
    const __nv_bfloat16* __restrict__ Ah, const __nv_bfloat16* __restrict__ Al,
    int lda, int rowA0,
    const __nv_bfloat16* __restrict__ Bh, const __nv_bfloat16* __restrict__ Bl,
    int ldb, int rowB0, int koff, int tid)
{
    int r0 = tid >> 2;           // 0..63
    int c0 = tid & 3;            // 16B chunk within row
    #pragma unroll
    for (int h = 0; h < 2; ++h) {
        int r = r0 + h * 64;
        uint32_t soff = (uint32_t)r * ROW_B + (uint32_t)c0 * 16u;
        size_t ga = (size_t)(rowA0 + r) * lda + koff + c0 * 8;
        cpasync16(sbase + soff,              Ah + ga);
        cpasync16(sbase + TILE_B + soff,     Al + ga);
        size_t gb = (size_t)(rowB0 + r) * ldb + koff + c0 * 8;
        cpasync16(sbase + 2u*TILE_B + soff,  Bh + gb);
        cpasync16(sbase + 3u*TILE_B + soff,  Bl + gb);
    }
}

// ------------------------- compute one BK=32 chunk -------------------------
// Register-lean ordering: all B frags hoisted per k-slice (16 regs), A frags
// streamed per m-tile (8 regs live), 12 MMAs issued per A-frag load.
__device__ __forceinline__ void compute_stage(
    uint32_t sbase, int warpM, int warpN, int lane, float acc[4][4][4])
{
    int mi    = lane >> 3;        // ldsm matrix index 0..3
    int tjo   = mi >> 1;          // n-tile within pair
    int khalf = mi & 1;           // k rows 0-7 / 8-15
    #pragma unroll
    for (int ks = 0; ks < 2; ++ks) {
        uint32_t bh[8], bl[8];    // [tj*2 + kreg]
        #pragma unroll
        for (int tp = 0; tp < 2; ++tp) {
            int brow = warpN * 32 + (tp * 2 + tjo) * 8 + (lane & 7);
            int bcol = ks * 16 + khalf * 8;
            uint32_t baddr = sbase + 2u*TILE_B + (uint32_t)brow * ROW_B
                           + (uint32_t)bcol * 2u;
            ldm_x4(bh + tp * 4, baddr);
            ldm_x4(bl + tp * 4, baddr + TILE_B);
        }
        int arow = warpM * 64 + (lane & 15);
        int acol = ks * 16 + (lane >> 4) * 8;
        #pragma unroll
        for (int ti = 0; ti < 4; ++ti) {
            uint32_t ah[4], al[4];
            uint32_t aaddr = sbase + (uint32_t)(arow + ti * 16) * ROW_B
                           + (uint32_t)acol * 2u;
            ldm_x4(ah, aaddr);
            ldm_x4(al, aaddr + TILE_B);
            #pragma unroll
            for (int tj = 0; tj < 4; ++tj) {
                mma16816(acc[ti][tj], ah, bh + tj * 2);
                mma16816(acc[ti][tj], ah, bl + tj * 2);
                mma16816(acc[ti][tj], al, bh + tj * 2);
            }
        }
    }
}

// ------------------------- pipelined mainloop (single sync/chunk) ----------
__device__ __forceinline__ void gemm_mainloop(
    float acc[4][4][4],
    const __nv_bfloat16* __restrict__ Ah, const __nv_bfloat16* __restrict__ Al,
    int lda, int rowA0,
    const __nv_bfloat16* __restrict__ Bh, const __nv_bfloat16* __restrict__ Bl,
    int ldb, int rowB0, int kTotal, uint32_t sb, int tid)
{
    int nC   = kTotal / BK;
    int lane = tid & 31, warp = tid >> 5;
    int warpM = warp >> 2, warpN = warp & 3;   // 2 x 4

    load_stage(sb, Ah, Al, lda, rowA0, Bh, Bl, ldb, rowB0, 0, tid);
    CP_COMMIT();
    for (int c = 0; c < nC; ++c) {
        CP_WAIT0();          // data for chunk c landed (issued last iteration)
        __syncthreads();     // all warps done with the buffer we're about to refill
        if (c + 1 < nC) {
            load_stage(sb + (uint32_t)((c + 1) & 1) * STAGE_B,
                       Ah, Al, lda, rowA0, Bh, Bl, ldb, rowB0, (c + 1) * BK, tid);
            CP_COMMIT();
        }
        compute_stage(sb + (uint32_t)(c & 1) * STAGE_B, warpM, warpN, lane, acc);
    }
}

// ------------------------- conversion kernels -------------------------
__global__ void k_split(const float* __restrict__ x, __nv_bfloat16* __restrict__ h,
                        __nv_bfloat16* __restrict__ l, int n4)
{
    int i = blockIdx.x * blockDim.x + threadIdx.x;
    if (i >= n4) return;
    float4 v = ((const float4*)x)[i];
    __nv_bfloat16 h0,h1,h2,h3, l0,l1,l2,l3;
    split1(v.x, h0, l0); split1(v.y, h1, l1);
    split1(v.z, h2, l2); split1(v.w, h3, l3);
    ((__nv_bfloat162*)h)[2*i]   = __nv_bfloat162(h0, h1);
    ((__nv_bfloat162*)h)[2*i+1] = __nv_bfloat162(h2, h3);
    ((__nv_bfloat162*)l)[2*i]   = __nv_bfloat162(l0, l1);
    ((__nv_bfloat162*)l)[2*i+1] = __nv_bfloat162(l2, l3);
}

__global__ void k_transpose_split(const float* __restrict__ Wout)
{
    __shared__ float tile[32][33];
    int x = blockIdx.x * 32 + threadIdx.x;   // g
    int y = blockIdx.y * 32 + threadIdx.y;   // p
    #pragma unroll
    for (int i = 0; i < 32; i += 8)
        tile[threadIdx.y + i][threadIdx.x] = Wout[(size_t)(y + i) * NG + x];
    __syncthreads();
    int xo = blockIdx.y * 32 + threadIdx.x;  // p
    int yo = blockIdx.x * 32 + threadIdx.y;  // g
    #pragma unroll
    for (int i = 0; i < 32; i += 8) {
        float v = tile[threadIdx.x][threadIdx.y + i];
        __nv_bfloat16 h, l; split1(v, h, l);
        g_WTh[(size_t)(yo + i) * NP + xo] = h;
        g_WTl[(size_t)(yo + i) * NP + xo] = l;
    }
}

// ------------------------- GEMM kernels -------------------------
// K1: G = tanh(prev_z @ Wr^T + v @ Win^T); z = G; split z -> bf16 hi/lo
__global__ __launch_bounds__(256, 2) void k_gval()
{
    extern __shared__ char smem[];
    uint32_t sb = smem_u32(smem);
    int tid = threadIdx.x;
    int lane = tid & 31, warp = tid >> 5;
    int warpM = warp >> 2, warpN = warp & 3;
    int rowA0 = blockIdx.y * 128, colB0 = blockIdx.x * 128;

    float acc[4][4][4];
    #pragma unroll
    for (int a = 0; a < 4; ++a)
        #pragma unroll
        for (int b = 0; b < 4; ++b)
            #pragma unroll
            for (int c = 0; c < 4; ++c) acc[a][b][c] = 0.f;

    gemm_mainloop(acc, g_pzh, g_pzl, NG, rowA0, g_Wrh,  g_Wrl,  NG, colB0, NG, sb, tid);
    gemm_mainloop(acc, g_vh,  g_vl,  NV, rowA0, g_Winh, g_Winl, NV, colB0, NV, sb, tid);

    #pragma unroll
    for (int ti = 0; ti < 4; ++ti) {
        int rbase = rowA0 + warpM * 64 + ti * 16 + (lane >> 2);
        #pragma unroll
        for (int tj = 0; tj < 4; ++tj) {
            int cc = colB0 + warpN * 32 + tj * 8 + (lane & 3) * 2;
            #pragma unroll
            for (int h = 0; h < 2; ++h) {
                int row = rbase + h * 8;
                float t0 = tanhf(acc[ti][tj][2*h]);
                float t1 = tanhf(acc[ti][tj][2*h+1]);
                size_t idx = (size_t)row * NG + cc;
                *(float2*)(g_G + idx) = make_float2(t0, t1);
                *(float2*)(g_z + idx) = make_float2(t0, t1);
                __nv_bfloat16 h0,h1,l0,l1;
                split1(t0, h0, l0); split1(t1, h1, l1);
                *(__nv_bfloat162*)(g_zh + idx) = __nv_bfloat162(h0, h1);
                *(__nv_bfloat162*)(g_zl + idx) = __nv_bfloat162(l0, l1);
            }
        }
    }
}

// K2: pred = tanh(z @ Wout^T); E = (1-pred^2)(p-pred); split E -> bf16 hi/lo
__global__ __launch_bounds__(256, 2) void k_pred(const float* __restrict__ p)
{
    extern __shared__ char smem[];
    uint32_t sb = smem_u32(smem);
    int tid = threadIdx.x;
    int lane = tid & 31, warp = tid >> 5;
    int warpM = warp >> 2, warpN = warp & 3;
    int rowA0 = blockIdx.y * 128, colB0 = blockIdx.x * 128;

    float acc[4][4][4];
    #pragma unroll
    for (int a = 0; a < 4; ++a)
        #pragma unroll
        for (int b = 0; b < 4; ++b)
            #pragma unroll
            for (int c = 0; c < 4; ++c) acc[a][b][c] = 0.f;

    gemm_mainloop(acc, g_zh, g_zl, NG, rowA0, g_Wouth, g_Woutl, NG, colB0, NG, sb, tid);

    #pragma unroll
    for (int ti = 0; ti < 4; ++ti) {
        int rbase = rowA0 + warpM * 64 + ti * 16 + (lane >> 2);
        #pragma unroll
        for (int tj = 0; tj < 4; ++tj) {
            int cc = colB0 + warpN * 32 + tj * 8 + (lane & 3) * 2;
            #pragma unroll
            for (int h = 0; h < 2; ++h) {
                int row = rbase + h * 8;
                size_t idx = (size_t)row * NP + cc;
                float2 pv = *(const float2*)(p + idx);
                float pr0 = tanhf(acc[ti][tj][2*h]);
                float pr1 = tanhf(acc[ti][tj][2*h+1]);
                float e0 = (1.0f - pr0*pr0) * (pv.x - pr0);
                float e1 = (1.0f - pr1*pr1) * (pv.y - pr1);
                __nv_bfloat16 h0,h1,l0,l1;
                split1(e0, h0, l0); split1(e1, h1, l1);
                *(__nv_bfloat162*)(g_Eh + idx) = __nv_bfloat162(h0, h1);
                *(__nv_bfloat162*)(g_El + idx) = __nv_bfloat162(l0, l1);
            }
        }
    }
}

// K3: U = E @ WT^T; z -= lr*((z-G) - U + lambda*sign(z)); re-split z
__global__ __launch_bounds__(256, 2) void k_update(const int* __restrict__ n_iters, int iter)
{
    int n = *n_iters;
    if (iter >= n) return;
    bool need_split = (iter + 1 < n);   // last iteration: zh/zl have no consumer
    extern __shared__ char smem[];
    uint32_t sb = smem_u32(smem);
    int tid = threadIdx.x;
    int lane = tid & 31, warp = tid >> 5;
    int warpM = warp >> 2, warpN = warp & 3;
    int rowA0 = blockIdx.y * 128, colB0 = blockIdx.x * 128;

    float acc[4][4][4];
    #pragma unroll
    for (int a = 0; a < 4; ++a)
        #pragma unroll
        for (int b = 0; b < 4; ++b)
            #pragma unroll
            for (int c = 0; c < 4; ++c) acc[a][b][c] = 0.f;

    gemm_mainloop(acc, g_Eh, g_El, NP, rowA0, g_WTh, g_WTl, NP, colB0, NP, sb, tid);

    #pragma unroll
    for (int ti = 0; ti < 4; ++ti) {
        int rbase = rowA0 + warpM * 64 + ti * 16 + (lane >> 2);
        #pragma unroll
        for (int tj = 0; tj < 4; ++tj) {
            int cc = colB0 + warpN * 32 + tj * 8 + (lane & 3) * 2;
            #pragma unroll
            for (int h = 0; h < 2; ++h) {
                int row = rbase + h * 8;
                size_t idx = (size_t)row * NG + cc;
                float2 zv = *(const float2*)(g_z + idx);
                float2 gv = *(const float2*)(g_G + idx);
                float u0 = acc[ti][tj][2*h], u1 = acc[ti][tj][2*h+1];
                float s0 = (zv.x > 0.f) ? 1.f : ((zv.x < 0.f) ? -1.f : 0.f);
                float s1 = (zv.y > 0.f) ? 1.f : ((zv.y < 0.f) ? -1.f : 0.f);
                float zn0 = zv.x - INF_LR * ((zv.x - gv.x) - u0 + LAMBDA_Z * s0);
                float zn1 = zv.y - INF_LR * ((zv.y - gv.y) - u1 + LAMBDA_Z * s1);
                *(float2*)(g_z + idx) = make_float2(zn0, zn1);
                if (need_split) {
                    __nv_bfloat16 h0,h1,l0,l1;
                    split1(zn0, h0, l0); split1(zn1, h1, l1);
                    *(__nv_bfloat162*)(g_zh + idx) = __nv_bfloat162(h0, h1);
                    *(__nv_bfloat162*)(g_zl + idx) = __nv_bfloat162(l0, l1);
                }
            }
        }
    }
}

__global__ void k_out(float* __restrict__ out)
{
    size_t i = (size_t)blockIdx.x * blockDim.x + threadIdx.x;
    ((float4*)out)[i] = ((const float4*)g_z)[i];
}

// ---------------------------------------------------------------------------
extern "C" void kernel_launch(void* const* d_in, const int* in_sizes, int n_in,
                              void* d_out, int out_size)
{
    const float* v      = (const float*)d_in[0];
    const float* prev_z = (const float*)d_in[1];
    const float* p      = (const float*)d_in[2];
    const float* Wr     = (const float*)d_in[3];
    const float* Win    = (const float*)d_in[4];
    const float* Wout   = (const float*)d_in[5];
    const int*   iters  = (const int*)d_in[6];

    static bool attr_done = false;
    if (!attr_done) {
        cudaFuncSetAttribute(k_gval,   cudaFuncAttributeMaxDynamicSharedMemorySize, SMEM_TOTAL);
        cudaFuncSetAttribute(k_pred,   cudaFuncAttributeMaxDynamicSharedMemorySize, SMEM_TOTAL);
        cudaFuncSetAttribute(k_update, cudaFuncAttributeMaxDynamicSharedMemorySize, SMEM_TOTAL);
        attr_done = true;
    }

    __nv_bfloat16 *vh, *vl, *pzh, *pzl, *wrh, *wrl, *winh, *winl, *woh, *wol;
    cudaGetSymbolAddress((void**)&vh,  g_vh);  cudaGetSymbolAddress((void**)&vl,  g_vl);
    cudaGetSymbolAddress((void**)&pzh, g_pzh); cudaGetSymbolAddress((void**)&pzl, g_pzl);
    cudaGetSymbolAddress((void**)&wrh, g_Wrh); cudaGetSymbolAddress((void**)&wrl, g_Wrl);
    cudaGetSymbolAddress((void**)&winh,g_Winh);cudaGetSymbolAddress((void**)&winl,g_Winl);
    cudaGetSymbolAddress((void**)&woh, g_Wouth);cudaGetSymbolAddress((void**)&wol, g_Woutl);

    auto split = [](const float* x, __nv_bfloat16* h, __nv_bfloat16* l, int n) {
        int n4 = n / 4;
        k_split<<<(n4 + 255) / 256, 256>>>(x, h, l, n4);
    };
    split(v,      vh,  vl,  B_DIM * NV);
    split(prev_z, pzh, pzl, B_DIM * NG);
    split(Wr,     wrh, wrl, NG * NG);
    split(Win,    winh,winl,NG * NV);
    split(Wout,   woh, wol, NP * NG);
    k_transpose_split<<<dim3(NG / 32, NP / 32), dim3(32, 8)>>>(Wout);

    dim3 blk(256);
    dim3 gridG(NG / 128, B_DIM / 128);   // 16 x 32
    dim3 gridP(NP / 128, B_DIM / 128);   // 8 x 32

    k_gval<<<gridG, blk, SMEM_TOTAL>>>();
    k_pred<<<gridP, blk, SMEM_TOTAL>>>(p);
    for (int it = 0; it < MAX_ITERS; ++it) {
        k_update<<<gridG, blk, SMEM_TOTAL>>>(iters, it);
        if (it + 1 < MAX_ITERS)
            k_pred<<<gridP, blk, SMEM_TOTAL>>>(p);
    }
    k_out<<<(B_DIM * NG / 4) / 256, 256>>>((float*)d_out);
}